// round 12
// baseline (speedup 1.0000x reference)
#include <cuda_runtime.h>
#include <cuda_fp16.h>
#include <math.h>
#include <float.h>
#include <stdint.h>

// Problem constants
#define B_SZ     2
#define N_PTS    4096
#define M_VOX    2048
#define D_MODEL  256
#define NHEADS   8
#define HD       32
#define NTILES   (M_VOX / 64)

// Scratch (device globals: allocation-free per harness rules)
__device__ __half g_k16 [B_SZ * NHEADS * M_VOX * HD];     // [(bh), M, 32]
__device__ __half g_v16 [B_SZ * NHEADS * HD * M_VOX];     // [(bh), 32, M] transposed
__device__ __half g_vox16[B_SZ * M_VOX * D_MODEL];        // voxel fp16
__device__ __half g_wk16[D_MODEL * D_MODEL];              // Wk fp16
__device__ __half g_wv16[D_MODEL * D_MODEL];              // Wv fp16
__device__ __half g_wf16[D_MODEL * D_MODEL];              // Wf2 fp16 (cols 256..511)
__device__ __half g_att16[B_SZ * N_PTS * D_MODEL];        // normalized attended fp16
__device__ float  g_wqp[D_MODEL * 3];                     // (Wq@Wp) * QS
__device__ float  g_bqp[D_MODEL];                         // (Wq@bp + bq) * QS
__device__ float  g_wfp[D_MODEL * 3];                     // Wf1@Wp
__device__ float  g_bfp[D_MODEL];                         // Wf1@bp + bf

// ---------------------------------------------------------------------------
// Helpers
// ---------------------------------------------------------------------------
__device__ __forceinline__ uint32_t f16pair(float lo, float hi) {
    uint32_t r;
    asm("cvt.rn.f16x2.f32 %0, %1, %2;" : "=r"(r) : "f"(hi), "f"(lo));
    return r;
}
__device__ __forceinline__ uint32_t ex2h2(uint32_t x) {
    uint32_t y;
    asm("ex2.approx.f16x2 %0, %1;" : "=r"(y) : "r"(x));
    return y;
}
__device__ __forceinline__ void mma_f16(float* d, const uint32_t* a, uint32_t b0, uint32_t b1) {
    asm volatile(
        "mma.sync.aligned.m16n8k16.row.col.f32.f16.f16.f32 "
        "{%0,%1,%2,%3}, {%4,%5,%6,%7}, {%8,%9}, {%0,%1,%2,%3};\n"
        : "+f"(d[0]), "+f"(d[1]), "+f"(d[2]), "+f"(d[3])
        : "r"(a[0]), "r"(a[1]), "r"(a[2]), "r"(a[3]),
          "r"(b0), "r"(b1));
}
__device__ __forceinline__ void ldsm4(uint32_t* r, uint32_t addr) {
    asm volatile("ldmatrix.sync.aligned.m8n8.x4.shared.b16 {%0,%1,%2,%3}, [%4];"
        : "=r"(r[0]), "=r"(r[1]), "=r"(r[2]), "=r"(r[3]) : "r"(addr));
}
__device__ __forceinline__ void cp16(void* dst, const void* src) {
    uint32_t s = (uint32_t)__cvta_generic_to_shared(dst);
    asm volatile("cp.async.ca.shared.global [%0], [%1], 16;" :: "r"(s), "l"(src));
}
#define CP_COMMIT()  asm volatile("cp.async.commit_group;")
#define CP_WAIT(N)   asm volatile("cp.async.wait_group %0;" :: "n"(N))

// ---------------------------------------------------------------------------
// Prep: fold Wp/bp through Wq (with softmax scale*log2e) and through Wf1.
// ---------------------------------------------------------------------------
__global__ void __launch_bounds__(256) prep_kernel(const float* __restrict__ Wp,
                                                   const float* __restrict__ bp,
                                                   const float* __restrict__ Wq,
                                                   const float* __restrict__ bq,
                                                   const float* __restrict__ Wf,
                                                   const float* __restrict__ bf) {
    const float QS = 0.17677669529663689f * 1.44269504088896340f;
    const int e    = blockIdx.x * 8 + (threadIdx.x >> 5);
    const int lane = threadIdx.x & 31;
    float sum = 0.0f;

    if (e < 768) {
        const int c = e / 3, j = e - 3 * c;
        const float* wq = Wq + c * 256;
        for (int d = lane; d < 256; d += 32) sum += wq[d] * Wp[d * 3 + j];
#pragma unroll
        for (int m = 16; m; m >>= 1) sum += __shfl_xor_sync(0xffffffffu, sum, m);
        if (lane == 0) g_wqp[e] = sum * QS;
    } else if (e < 1024) {
        const int c = e - 768;
        const float* wq = Wq + c * 256;
        for (int d = lane; d < 256; d += 32) sum += wq[d] * bp[d];
#pragma unroll
        for (int m = 16; m; m >>= 1) sum += __shfl_xor_sync(0xffffffffu, sum, m);
        if (lane == 0) g_bqp[c] = (sum + bq[c]) * QS;
    } else if (e < 1792) {
        const int e2 = e - 1024;
        const int c = e2 / 3, j = e2 - 3 * c;
        const float* wf = Wf + (size_t)c * 512;
        for (int d = lane; d < 256; d += 32) sum += wf[d] * Wp[d * 3 + j];
#pragma unroll
        for (int m = 16; m; m >>= 1) sum += __shfl_xor_sync(0xffffffffu, sum, m);
        if (lane == 0) g_wfp[e2] = sum;
    } else {
        const int c = e - 1792;
        const float* wf = Wf + (size_t)c * 512;
        for (int d = lane; d < 256; d += 32) sum += wf[d] * bp[d];
#pragma unroll
        for (int m = 16; m; m >>= 1) sum += __shfl_xor_sync(0xffffffffu, sum, m);
        if (lane == 0) g_bfp[c] = sum + bf[c];
    }
}

// ---------------------------------------------------------------------------
// Convert voxel + weights to fp16.
// ---------------------------------------------------------------------------
__global__ void __launch_bounds__(256) cvt_kernel(const float* __restrict__ voxel,
                                                  const float* __restrict__ Wk,
                                                  const float* __restrict__ Wv,
                                                  const float* __restrict__ Wf) {
    const int i = blockIdx.x * 256 + threadIdx.x;
    if (i < B_SZ * M_VOX * D_MODEL) g_vox16[i] = __float2half_rn(voxel[i]);
    if (i < D_MODEL * D_MODEL) {
        g_wk16[i] = __float2half_rn(Wk[i]);
        g_wv16[i] = __float2half_rn(Wv[i]);
        const int r = i >> 8, c = i & 255;
        g_wf16[i] = __float2half_rn(Wf[(size_t)r * 512 + 256 + c]);
    }
}

// ---------------------------------------------------------------------------
// fp16 MMA GEMM: C[rows,256] = A[rows,256] @ W[256,256]^T (+ epilogue)
//   64x64 tile, 128 threads, BK=32, 3-stage cp.async ring, 1 barrier/iter.
//   MODE 1: kv projection, z=0 -> g_k16 row-major, z=1 -> g_v16 transposed.
//   MODE 0: final gemm -> row-major f32 + g_bfp + pts@g_wfp^T fold.
// ---------------------------------------------------------------------------
template <int MODE>
__global__ void __launch_bounds__(128) gemm_f16(const __half* __restrict__ A,
                                                const __half* __restrict__ W1,
                                                const __half* __restrict__ W2,
                                                const float* __restrict__ bias1,
                                                const float* __restrict__ bias2,
                                                float* __restrict__ C,
                                                const float* __restrict__ pts) {
    __shared__ __half As[3][64][40];
    __shared__ __half Ws[3][64][40];

    const int zv = (MODE == 1) ? blockIdx.z : 0;
    const __half* W   = zv ? W2    : W1;
    const float* bias = zv ? bias2 : bias1;

    const int tid  = threadIdx.x;
    const int lane = tid & 31;
    const int warp = tid >> 5;
    const int g    = lane >> 2;
    const int t    = lane & 3;
    const int rb   = warp * 16;
    const int col0 = blockIdx.x * 64;
    const int row0 = blockIdx.y * 64;
    const int mm   = lane >> 3;
    const int rr   = lane & 7;

    uint32_t asb[3], wsb[3];
#pragma unroll
    for (int i = 0; i < 3; i++) {
        asb[i] = (uint32_t)__cvta_generic_to_shared(&As[i][0][0]);
        wsb[i] = (uint32_t)__cvta_generic_to_shared(&Ws[i][0][0]);
    }

    float s[8][4];
#pragma unroll
    for (int nb = 0; nb < 8; nb++)
#pragma unroll
        for (int j = 0; j < 4; j++) s[nb][j] = 0.0f;

    auto load_tile = [&](int stg, int k0) {
#pragma unroll
        for (int i = 0; i < 2; i++) {
            const int idx = i * 128 + tid;
            const int r = idx >> 2, cs = (idx & 3) * 8;
            cp16(&As[stg][r][cs], A + (size_t)(row0 + r) * 256 + k0 + cs);
            cp16(&Ws[stg][r][cs], W + (size_t)(col0 + r) * 256 + k0 + cs);
        }
        CP_COMMIT();
    };

    load_tile(0, 0);
    load_tile(1, 32);

    int st = 0, st2 = 2;
    for (int it = 0; it < 8; it++) {
        if (it + 1 < 8) { CP_WAIT(1); } else { CP_WAIT(0); }
        __syncthreads();
        if (it + 2 < 8) load_tile(st2, (it + 2) * 32);

#pragma unroll
        for (int kk = 0; kk < 2; kk++) {
            uint32_t a[4];
            ldsm4(a, asb[st] + 2 * ((rb + 8 * (mm & 1) + rr) * 40 + 16 * kk + 8 * (mm >> 1)));
#pragma unroll
            for (int q = 0; q < 4; q++) {
                uint32_t wb[4];
                ldsm4(wb, wsb[st] + 2 * ((16 * q + 8 * (mm >> 1) + rr) * 40 + 16 * kk + 8 * (mm & 1)));
                mma_f16(s[2 * q    ], a, wb[0], wb[1]);
                mma_f16(s[2 * q + 1], a, wb[2], wb[3]);
            }
        }
        st = (st == 2) ? 0 : st + 1;
        st2 = (st2 == 2) ? 0 : st2 + 1;
    }

    // epilogue (fp32 accumulators)
    const int r0 = row0 + rb + g;
    const int r1 = r0 + 8;
    float p00 = 0, p01 = 0, p02 = 0, p10 = 0, p11 = 0, p12 = 0;
    if (MODE == 0) {
        p00 = pts[r0 * 3 + 0]; p01 = pts[r0 * 3 + 1]; p02 = pts[r0 * 3 + 2];
        p10 = pts[r1 * 3 + 0]; p11 = pts[r1 * 3 + 1]; p12 = pts[r1 * 3 + 2];
    }
#pragma unroll
    for (int nb = 0; nb < 8; nb++) {
        const int c = col0 + nb * 8 + 2 * t;
        if (MODE == 1) {
            const float b0 = bias[c], b1 = bias[c + 1];
            const int b_  = r0 >> 11;
            const int n0_ = r0 & (M_VOX - 1), n1_ = r1 & (M_VOX - 1);
            const int h = c >> 5, dh = c & 31;
            const int bh = b_ * NHEADS + h;
            if (zv == 0) {   // K: row-major fp16
                __half* dst0 = g_k16 + ((size_t)bh * M_VOX + n0_) * HD + dh;
                __half* dst1 = g_k16 + ((size_t)bh * M_VOX + n1_) * HD + dh;
                *(__half2*)dst0 = __floats2half2_rn(s[nb][0] + b0, s[nb][1] + b1);
                *(__half2*)dst1 = __floats2half2_rn(s[nb][2] + b0, s[nb][3] + b1);
            } else {         // V: transposed fp16 [bh][dh][M]
                __half* r_lo = g_v16 + ((size_t)bh * HD + dh    ) * M_VOX;
                __half* r_hi = g_v16 + ((size_t)bh * HD + dh + 1) * M_VOX;
                r_lo[n0_] = __float2half_rn(s[nb][0] + b0);
                r_hi[n0_] = __float2half_rn(s[nb][1] + b1);
                r_lo[n1_] = __float2half_rn(s[nb][2] + b0);
                r_hi[n1_] = __float2half_rn(s[nb][3] + b1);
            }
        } else {
            const float b0 = g_bfp[c], b1 = g_bfp[c + 1];
            const float w00 = g_wfp[c * 3 + 0], w01 = g_wfp[c * 3 + 1], w02 = g_wfp[c * 3 + 2];
            const float w10 = g_wfp[c * 3 + 3], w11 = g_wfp[c * 3 + 4], w12 = g_wfp[c * 3 + 5];
            float v00 = s[nb][0] + b0 + p00 * w00 + p01 * w01 + p02 * w02;
            float v01 = s[nb][1] + b1 + p00 * w10 + p01 * w11 + p02 * w12;
            float v10 = s[nb][2] + b0 + p10 * w00 + p11 * w01 + p12 * w02;
            float v11 = s[nb][3] + b1 + p10 * w10 + p11 * w11 + p12 * w12;
            *(float2*)(C + (size_t)r0 * 256 + c) = make_float2(v00, v01);
            *(float2*)(C + (size_t)r1 * 256 + c) = make_float2(v10, v11);
        }
    }
}

// ---------------------------------------------------------------------------
// Flash attention, full KV per CTA, 128-row Q tile, 4 warps x 32 rows.
// Cross-tile software pipeline: per 16-kv-col block, interleave
//   ex2 of tile i  |  S-HMMAs of tile i+1  |  PV-HMMAs of tile i
// so MUFU hides under the tensor stream despite per-tile barriers.
// 3-stage cp.async ring; writes normalized fp16 att directly.
// ---------------------------------------------------------------------------
__global__ void __launch_bounds__(128) attn_kernel(const float* __restrict__ pts) {
    const int h  = blockIdx.y;
    const int b  = blockIdx.z;
    const int bh = b * NHEADS + h;
    const int n0 = blockIdx.x * 128;

    const __half* __restrict__ Kp = g_k16 + (size_t)bh * M_VOX * HD;
    const __half* __restrict__ Vp = g_v16 + (size_t)bh * HD * M_VOX;

    __shared__ __half Ks[3][64][40];
    __shared__ __half Vt[3][32][72];

    const int tid  = threadIdx.x;
    const int lane = tid & 31;
    const int warp = tid >> 5;
    const int g    = lane >> 2;
    const int t    = lane & 3;
    const int rb   = warp * 32;
    const int mm   = lane >> 3;
    const int rr   = lane & 7;

    const uint32_t ks_row = 8 * (mm >> 1) + rr;
    const uint32_t ks_col = 8 * (mm & 1);
    uint32_t ksb[3], vtb[3];
#pragma unroll
    for (int i = 0; i < 3; i++) {
        ksb[i] = (uint32_t)__cvta_generic_to_shared(&Ks[i][0][0]);
        vtb[i] = (uint32_t)__cvta_generic_to_shared(&Vt[i][0][0]);
    }

    // ---- Q fragments from points (q = pts @ Wqp^T + bqp, scale folded)
    float P[4][3];
#pragma unroll
    for (int i = 0; i < 4; i++) {
        const int n = n0 + rb + 8 * i + g;
#pragma unroll
        for (int j = 0; j < 3; j++)
            P[i][j] = pts[((size_t)b * N_PTS + n) * 3 + j];
    }
    uint32_t qa[2][2][4];
#pragma unroll
    for (int kk = 0; kk < 2; kk++) {
#pragma unroll
        for (int hw = 0; hw < 2; hw++) {
            const int c = h * HD + 16 * kk + 8 * hw + 2 * t;
            const float wa0 = g_wqp[3 * c + 0], wa1 = g_wqp[3 * c + 1], wa2 = g_wqp[3 * c + 2];
            const float wb0 = g_wqp[3 * c + 3], wb1 = g_wqp[3 * c + 4], wb2 = g_wqp[3 * c + 5];
            const float ba = g_bqp[c], bb = g_bqp[c + 1];
#pragma unroll
            for (int grp = 0; grp < 2; grp++) {
#pragma unroll
                for (int rw = 0; rw < 2; rw++) {
                    const float* p = P[2 * grp + rw];
                    float q0 = fmaf(p[0], wa0, fmaf(p[1], wa1, fmaf(p[2], wa2, ba)));
                    float q1 = fmaf(p[0], wb0, fmaf(p[1], wb1, fmaf(p[2], wb2, bb)));
                    qa[grp][kk][rw + 2 * hw] = f16pair(q0, q1);
                }
            }
        }
    }

    float o[2][4][4];
    float lsum[2][2];
#pragma unroll
    for (int grp = 0; grp < 2; grp++) {
        lsum[grp][0] = 0.0f; lsum[grp][1] = 0.0f;
#pragma unroll
        for (int nb = 0; nb < 4; nb++)
#pragma unroll
            for (int j = 0; j < 4; j++) o[grp][nb][j] = 0.0f;
    }

    auto load_tile = [&](int stg, int j0) {
#pragma unroll
        for (int i = 0; i < 2; i++) {
            const int idx = i * 128 + tid;
            const int rK = idx >> 2, cK = (idx & 3) * 8;
            cp16(&Ks[stg][rK][cK], Kp + (size_t)(j0 + rK) * HD + cK);
            const int rV = idx >> 3, cV = (idx & 7) * 8;
            cp16(&Vt[stg][rV][cV], Vp + (size_t)rV * M_VOX + j0 + cV);
        }
        CP_COMMIT();
    };

    // prologue: tiles 0,1
    load_tile(0, 0);
    load_tile(1, 64);
    CP_WAIT(1);          // tile 0 resident (tile 1 in flight)
    __syncthreads();

    // S for tile 0
    float s[2][8][4];
#pragma unroll
    for (int grp = 0; grp < 2; grp++)
#pragma unroll
        for (int nb = 0; nb < 8; nb++)
#pragma unroll
            for (int j = 0; j < 4; j++) s[grp][nb][j] = 0.0f;
#pragma unroll
    for (int kk = 0; kk < 2; kk++) {
#pragma unroll
        for (int q = 0; q < 4; q++) {
            uint32_t kb[4];
            ldsm4(kb, ksb[0] + 2 * ((16 * q + ks_row) * 40 + 16 * kk + ks_col));
#pragma unroll
            for (int grp = 0; grp < 2; grp++) {
                mma_f16(s[grp][2 * q    ], qa[grp][kk], kb[0], kb[1]);
                mma_f16(s[grp][2 * q + 1], qa[grp][kk], kb[2], kb[3]);
            }
        }
    }

    for (int it = 0; it < NTILES; it++) {
        const int cur = it % 3;
        const int nxt = (it + 1) % 3;
        const bool have_next = (it + 1 < NTILES);

        __syncthreads();                       // tile it-1 fully consumed by all warps
        if (it + 2 < NTILES) {
            load_tile((it + 2) % 3, (it + 2) * 64);
            CP_WAIT(1);                        // tile it+1 resident (it+2 in flight)
        } else {
            CP_WAIT(0);                        // drain (covers it+1 if it exists)
        }

        __half2 lt[2][2];
#pragma unroll
        for (int grp = 0; grp < 2; grp++) {
            lt[grp][0] = __floats2half2_rn(0.0f, 0.0f);
            lt[grp][1] = __floats2half2_rn(0.0f, 0.0f);
        }

#pragma unroll
        for (int blk = 0; blk < 4; blk++) {
            // 1) P for kv block blk of tile it (reads s rows 2blk,2blk+1)
            uint32_t pa[2][4];
#pragma unroll
            for (int grp = 0; grp < 2; grp++) {
                pa[grp][0] = ex2h2(f16pair(s[grp][2 * blk    ][0], s[grp][2 * blk    ][1]));
                pa[grp][1] = ex2h2(f16pair(s[grp][2 * blk    ][2], s[grp][2 * blk    ][3]));
                pa[grp][2] = ex2h2(f16pair(s[grp][2 * blk + 1][0], s[grp][2 * blk + 1][1]));
                pa[grp][3] = ex2h2(f16pair(s[grp][2 * blk + 1][2], s[grp][2 * blk + 1][3]));
                lt[grp][0] = __hadd2(lt[grp][0],
                    __hadd2(*(__half2*)&pa[grp][0], *(__half2*)&pa[grp][2]));
                lt[grp][1] = __hadd2(lt[grp][1],
                    __hadd2(*(__half2*)&pa[grp][1], *(__half2*)&pa[grp][3]));
            }

            // 2) S of tile it+1, kv block blk (overwrites s rows 2blk,2blk+1)
            if (have_next) {
#pragma unroll
                for (int grp = 0; grp < 2; grp++)
#pragma unroll
                    for (int j = 0; j < 4; j++) {
                        s[grp][2 * blk][j] = 0.0f;
                        s[grp][2 * blk + 1][j] = 0.0f;
                    }
#pragma unroll
                for (int kk = 0; kk < 2; kk++) {
                    uint32_t kb[4];
                    ldsm4(kb, ksb[nxt] + 2 * ((16 * blk + ks_row) * 40 + 16 * kk + ks_col));
#pragma unroll
                    for (int grp = 0; grp < 2; grp++) {
                        mma_f16(s[grp][2 * blk    ], qa[grp][kk], kb[0], kb[1]);
                        mma_f16(s[grp][2 * blk + 1], qa[grp][kk], kb[2], kb[3]);
                    }
                }
            }

            // 3) O += P V for kv block blk of tile it
#pragma unroll
            for (int q = 0; q < 2; q++) {
                uint32_t vb[4];
                ldsm4(vb, vtb[cur] + 2 * ((16 * q + ks_row) * 72 + 16 * blk + ks_col));
#pragma unroll
                for (int grp = 0; grp < 2; grp++) {
                    mma_f16(o[grp][2 * q    ], pa[grp], vb[0], vb[1]);
                    mma_f16(o[grp][2 * q + 1], pa[grp], vb[2], vb[3]);
                }
            }
        }

#pragma unroll
        for (int grp = 0; grp < 2; grp++) {
            lsum[grp][0] += __low2float(lt[grp][0]) + __high2float(lt[grp][0]);
            lsum[grp][1] += __low2float(lt[grp][1]) + __high2float(lt[grp][1]);
        }
    }

    // endgame: reduce l over t lanes, normalize, write fp16 att
#pragma unroll
    for (int grp = 0; grp < 2; grp++) {
        float l0 = lsum[grp][0], l1 = lsum[grp][1];
        l0 += __shfl_xor_sync(0xffffffffu, l0, 1);
        l0 += __shfl_xor_sync(0xffffffffu, l0, 2);
        l1 += __shfl_xor_sync(0xffffffffu, l1, 1);
        l1 += __shfl_xor_sync(0xffffffffu, l1, 2);
        const float inv0 = 1.0f / l0;
        const float inv1 = 1.0f / l1;
        const int r0 = n0 + rb + 16 * grp + g;
        const int r1 = r0 + 8;
#pragma unroll
        for (int nb = 0; nb < 4; nb++) {
            const int col = h * HD + nb * 8 + 2 * t;
            *(__half2*)(g_att16 + (size_t)(b * N_PTS + r0) * D_MODEL + col) =
                __floats2half2_rn(o[grp][nb][0] * inv0, o[grp][nb][1] * inv0);
            *(__half2*)(g_att16 + (size_t)(b * N_PTS + r1) * D_MODEL + col) =
                __floats2half2_rn(o[grp][nb][2] * inv1, o[grp][nb][3] * inv1);
        }
    }
}

// ---------------------------------------------------------------------------
// kernel_launch
// ---------------------------------------------------------------------------
extern "C" void kernel_launch(void* const* d_in, const int* in_sizes, int n_in,
                              void* d_out, int out_size) {
    const float* points = (const float*)d_in[0];
    const float* voxel  = (const float*)d_in[1];
    const float* Wp     = (const float*)d_in[2];
    const float* bp     = (const float*)d_in[3];
    const float* Wq     = (const float*)d_in[4];
    const float* bq     = (const float*)d_in[5];
    const float* Wk     = (const float*)d_in[6];
    const float* bk     = (const float*)d_in[7];
    const float* Wv     = (const float*)d_in[8];
    const float* bv     = (const float*)d_in[9];
    const float* Wf     = (const float*)d_in[10];
    const float* bf     = (const float*)d_in[11];
    float* out = (float*)d_out;

    __half *vox_ptr, *wk_ptr, *wv_ptr, *wf_ptr, *att_ptr;
    cudaGetSymbolAddress((void**)&vox_ptr, g_vox16);
    cudaGetSymbolAddress((void**)&wk_ptr,  g_wk16);
    cudaGetSymbolAddress((void**)&wv_ptr,  g_wv16);
    cudaGetSymbolAddress((void**)&wf_ptr,  g_wf16);
    cudaGetSymbolAddress((void**)&att_ptr, g_att16);

    // max smem carveout for attn (idempotent host attribute)
    cudaFuncSetAttribute(attn_kernel,
                         cudaFuncAttributePreferredSharedMemoryCarveout,
                         cudaSharedmemCarveoutMaxShared);

    // 1. weight folding + fp16 conversions
    prep_kernel<<<256, 256>>>(Wp, bp, Wq, bq, Wf, bf);
    cvt_kernel<<<(B_SZ * M_VOX * D_MODEL + 255) / 256, 256>>>(voxel, Wk, Wv, Wf);

    // 2. k & v projections (fp16 MMA; z: 0->K row-major, 1->V transposed)
    {
        dim3 grid(D_MODEL / 64, (B_SZ * M_VOX) / 64, 2);
        gemm_f16<1><<<grid, 128>>>(vox_ptr, wk_ptr, wv_ptr, bk, bv, nullptr, nullptr);
    }
    // 3. attention (full KV, cross-tile pipelined, writes fp16 att)
    {
        dim3 grid(N_PTS / 128, NHEADS, B_SZ);
        attn_kernel<<<grid, 128>>>(points);
    }
    // 4. final: att @ Wf2^T + pts @ Wfp^T + bfp
    {
        dim3 grid(D_MODEL / 64, (B_SZ * N_PTS) / 64, 1);
        gemm_f16<0><<<grid, 128>>>(att_ptr, wf_ptr, nullptr, nullptr, nullptr, out, points);
    }
}

// round 13
// speedup vs baseline: 1.2628x; 1.2628x over previous
#include <cuda_runtime.h>
#include <cuda_fp16.h>
#include <math.h>
#include <float.h>
#include <stdint.h>

// Problem constants
#define B_SZ     2
#define N_PTS    4096
#define M_VOX    2048
#define D_MODEL  256
#define NHEADS   8
#define HD       32
#define NTILES   (M_VOX / 64)
#define HTILES   (NTILES / 2)

// Scratch (device globals: allocation-free per harness rules)
__device__ __half g_k16 [B_SZ * NHEADS * M_VOX * HD];     // [(bh), M, 32]
__device__ __half g_v16 [B_SZ * NHEADS * HD * M_VOX];     // [(bh), 32, M] transposed
__device__ __half g_vox16[B_SZ * M_VOX * D_MODEL];        // voxel fp16
__device__ __half g_wk16[D_MODEL * D_MODEL];              // Wk fp16
__device__ __half g_wv16[D_MODEL * D_MODEL];              // Wv fp16
__device__ __half g_wf16[D_MODEL * D_MODEL];              // Wf2 fp16 (cols 256..511)
__device__ float  g_po[2 * B_SZ * N_PTS * D_MODEL];       // unnormalized O partials
__device__ float  g_pl[2 * B_SZ * NHEADS * N_PTS];        // l partials
__device__ float  g_wqp[D_MODEL * 3];                     // (Wq@Wp) * QS
__device__ float  g_bqp[D_MODEL];                         // (Wq@bp + bq) * QS
__device__ float  g_wfp[D_MODEL * 3];                     // Wf1@Wp
__device__ float  g_bfp[D_MODEL];                         // Wf1@bp + bf

// ---------------------------------------------------------------------------
// Helpers
// ---------------------------------------------------------------------------
__device__ __forceinline__ uint32_t f16pair(float lo, float hi) {
    uint32_t r;
    asm("cvt.rn.f16x2.f32 %0, %1, %2;" : "=r"(r) : "f"(hi), "f"(lo));
    return r;
}
__device__ __forceinline__ uint32_t ex2h2(uint32_t x) {
    uint32_t y;
    asm("ex2.approx.f16x2 %0, %1;" : "=r"(y) : "r"(x));
    return y;
}
__device__ __forceinline__ void mma_f16(float* d, const uint32_t* a, uint32_t b0, uint32_t b1) {
    asm volatile(
        "mma.sync.aligned.m16n8k16.row.col.f32.f16.f16.f32 "
        "{%0,%1,%2,%3}, {%4,%5,%6,%7}, {%8,%9}, {%0,%1,%2,%3};\n"
        : "+f"(d[0]), "+f"(d[1]), "+f"(d[2]), "+f"(d[3])
        : "r"(a[0]), "r"(a[1]), "r"(a[2]), "r"(a[3]),
          "r"(b0), "r"(b1));
}
__device__ __forceinline__ void ldsm4(uint32_t* r, uint32_t addr) {
    asm volatile("ldmatrix.sync.aligned.m8n8.x4.shared.b16 {%0,%1,%2,%3}, [%4];"
        : "=r"(r[0]), "=r"(r[1]), "=r"(r[2]), "=r"(r[3]) : "r"(addr));
}
__device__ __forceinline__ void cp16(void* dst, const void* src) {
    uint32_t s = (uint32_t)__cvta_generic_to_shared(dst);
    asm volatile("cp.async.ca.shared.global [%0], [%1], 16;" :: "r"(s), "l"(src));
}
#define CP_COMMIT()  asm volatile("cp.async.commit_group;")
#define CP_WAIT(N)   asm volatile("cp.async.wait_group %0;" :: "n"(N))

// ---------------------------------------------------------------------------
// Merged prep (weight folding) + fp16 conversion. 4096 blocks x 256.
// Blocks 0..255 also fold Wp/bp through Wq (scale*log2e) and Wf1.
// ---------------------------------------------------------------------------
__global__ void __launch_bounds__(256) prep_cvt_kernel(const float* __restrict__ Wp,
                                                       const float* __restrict__ bp,
                                                       const float* __restrict__ Wq,
                                                       const float* __restrict__ bq,
                                                       const float* __restrict__ Wf,
                                                       const float* __restrict__ bf,
                                                       const float* __restrict__ voxel,
                                                       const float* __restrict__ Wk,
                                                       const float* __restrict__ Wv) {
    const int i = blockIdx.x * 256 + threadIdx.x;
    if (i < B_SZ * M_VOX * D_MODEL) g_vox16[i] = __float2half_rn(voxel[i]);
    if (i < D_MODEL * D_MODEL) {
        g_wk16[i] = __float2half_rn(Wk[i]);
        g_wv16[i] = __float2half_rn(Wv[i]);
        const int r = i >> 8, c = i & 255;
        g_wf16[i] = __float2half_rn(Wf[(size_t)r * 512 + 256 + c]);
    }

    if (blockIdx.x < 256) {
        const float QS = 0.17677669529663689f * 1.44269504088896340f;
        const int e    = blockIdx.x * 8 + (threadIdx.x >> 5);
        const int lane = threadIdx.x & 31;
        float sum = 0.0f;

        if (e < 768) {
            const int c = e / 3, j = e - 3 * c;
            const float* wq = Wq + c * 256;
            for (int d = lane; d < 256; d += 32) sum += wq[d] * Wp[d * 3 + j];
#pragma unroll
            for (int m = 16; m; m >>= 1) sum += __shfl_xor_sync(0xffffffffu, sum, m);
            if (lane == 0) g_wqp[e] = sum * QS;
        } else if (e < 1024) {
            const int c = e - 768;
            const float* wq = Wq + c * 256;
            for (int d = lane; d < 256; d += 32) sum += wq[d] * bp[d];
#pragma unroll
            for (int m = 16; m; m >>= 1) sum += __shfl_xor_sync(0xffffffffu, sum, m);
            if (lane == 0) g_bqp[c] = (sum + bq[c]) * QS;
        } else if (e < 1792) {
            const int e2 = e - 1024;
            const int c = e2 / 3, j = e2 - 3 * c;
            const float* wf = Wf + (size_t)c * 512;
            for (int d = lane; d < 256; d += 32) sum += wf[d] * Wp[d * 3 + j];
#pragma unroll
            for (int m = 16; m; m >>= 1) sum += __shfl_xor_sync(0xffffffffu, sum, m);
            if (lane == 0) g_wfp[e2] = sum;
        } else {
            const int c = e - 1792;
            const float* wf = Wf + (size_t)c * 512;
            for (int d = lane; d < 256; d += 32) sum += wf[d] * bp[d];
#pragma unroll
            for (int m = 16; m; m >>= 1) sum += __shfl_xor_sync(0xffffffffu, sum, m);
            if (lane == 0) g_bfp[c] = sum + bf[c];
        }
    }
}

// ---------------------------------------------------------------------------
// fp16 MMA GEMM: C[rows,256] = A[rows,256] @ W[256,256]^T (+ epilogue)
//   64x64 tile, 128 threads, BK=32, 3-stage ring, 1 barrier/iter.
//   MODE 1: kv projection, z=0 -> g_k16 row-major, z=1 -> g_v16 transposed.
//           A = g_vox16 via cp.async.
//   MODE 0: final gemm. A = normalize-on-load from g_po/g_pl (combine fused):
//           chunk c covers att cols [32c,32c+32) = exactly head c, so one l
//           per row per chunk. LDGs issued before MMA section, STS after.
//           Output: row-major f32 + g_bfp + pts@g_wfp^T fold.
// ---------------------------------------------------------------------------
template <int MODE>
__global__ void __launch_bounds__(128) gemm_f16(const __half* __restrict__ A,
                                                const __half* __restrict__ W1,
                                                const __half* __restrict__ W2,
                                                const float* __restrict__ bias1,
                                                const float* __restrict__ bias2,
                                                float* __restrict__ C,
                                                const float* __restrict__ pts) {
    __shared__ __half As[3][64][40];
    __shared__ __half Ws[3][64][40];

    const int zv = (MODE == 1) ? blockIdx.z : 0;
    const __half* W   = zv ? W2    : W1;
    const float* bias = zv ? bias2 : bias1;

    const int tid  = threadIdx.x;
    const int lane = tid & 31;
    const int warp = tid >> 5;
    const int g    = lane >> 2;
    const int t    = lane & 3;
    const int rb   = warp * 16;
    const int col0 = blockIdx.x * 64;
    const int row0 = blockIdx.y * 64;
    const int mm   = lane >> 3;
    const int rr   = lane & 7;

    uint32_t asb[3], wsb[3];
#pragma unroll
    for (int i = 0; i < 3; i++) {
        asb[i] = (uint32_t)__cvta_generic_to_shared(&As[i][0][0]);
        wsb[i] = (uint32_t)__cvta_generic_to_shared(&Ws[i][0][0]);
    }

    float s[8][4];
#pragma unroll
    for (int nb = 0; nb < 8; nb++)
#pragma unroll
        for (int j = 0; j < 4; j++) s[nb][j] = 0.0f;

    // --- W loader (cp.async, both modes) ---
    auto load_W = [&](int stg, int k0) {
#pragma unroll
        for (int i = 0; i < 2; i++) {
            const int idx = i * 128 + tid;
            const int r = idx >> 2, cs = (idx & 3) * 8;
            cp16(&Ws[stg][r][cs], W + (size_t)(col0 + r) * 256 + k0 + cs);
        }
    };
    // --- A loader MODE 1 (cp.async) ---
    auto load_A1 = [&](int stg, int k0) {
#pragma unroll
        for (int i = 0; i < 2; i++) {
            const int idx = i * 128 + tid;
            const int r = idx >> 2, cs = (idx & 3) * 8;
            cp16(&As[stg][r][cs], A + (size_t)(row0 + r) * 256 + k0 + cs);
        }
    };

    // --- A staging MODE 0 (combine fused): registers for 2 slots ---
    float4 xa0[2], xa1[2], xb0[2], xb1[2];
    float  lv[2];
    auto issue_A0 = [&](int chunk) {
#pragma unroll
        for (int i = 0; i < 2; i++) {
            const int idx = i * 128 + tid;
            const int r = idx >> 2, cs = (idx & 3) * 8;
            const int row = row0 + r;
            const int bb = row >> 12, nn = row & (N_PTS - 1);
            const float* p0 = g_po + (size_t)row * 256 + chunk * 32 + cs;
            const float* p1 = p0 + (size_t)B_SZ * N_PTS * D_MODEL;
            xa0[i] = *(const float4*)p0;
            xa1[i] = *(const float4*)(p0 + 4);
            xb0[i] = *(const float4*)p1;
            xb1[i] = *(const float4*)(p1 + 4);
            lv[i] = g_pl[((size_t)bb * NHEADS + chunk) * N_PTS + nn] +
                    g_pl[((size_t)(B_SZ + bb) * NHEADS + chunk) * N_PTS + nn];
        }
    };
    auto sts_A0 = [&](int chunk) {
        const int stg = chunk % 3;
#pragma unroll
        for (int i = 0; i < 2; i++) {
            const int idx = i * 128 + tid;
            const int r = idx >> 2, cs = (idx & 3) * 8;
            const float inv = 1.0f / lv[i];
            uint32_t h0 = f16pair((xa0[i].x + xb0[i].x) * inv, (xa0[i].y + xb0[i].y) * inv);
            uint32_t h1 = f16pair((xa0[i].z + xb0[i].z) * inv, (xa0[i].w + xb0[i].w) * inv);
            uint32_t h2 = f16pair((xa1[i].x + xb1[i].x) * inv, (xa1[i].y + xb1[i].y) * inv);
            uint32_t h3 = f16pair((xa1[i].z + xb1[i].z) * inv, (xa1[i].w + xb1[i].w) * inv);
            *(uint4*)&As[stg][r][cs] = make_uint4(h0, h1, h2, h3);
        }
    };

    // --- prologue: chunks 0,1 ---
    if (MODE == 1) {
        load_A1(0, 0);  load_W(0, 0);  CP_COMMIT();
        load_A1(1, 32); load_W(1, 32); CP_COMMIT();
    } else {
        issue_A0(0); sts_A0(0);
        issue_A0(1); sts_A0(1);
        load_W(0, 0);  CP_COMMIT();
        load_W(1, 32); CP_COMMIT();
    }

    for (int it = 0; it < 8; it++) {
        const int st = it % 3;
        if (it + 1 < 8) { CP_WAIT(1); } else { CP_WAIT(0); }
        __syncthreads();
        const bool stage_more = (it + 2 < 8);
        if (stage_more) {
            if (MODE == 1) {
                load_A1((it + 2) % 3, (it + 2) * 32);
            } else {
                issue_A0(it + 2);           // LDGs in flight during MMAs
            }
            load_W((it + 2) % 3, (it + 2) * 32);
            CP_COMMIT();
        }

#pragma unroll
        for (int kk = 0; kk < 2; kk++) {
            uint32_t a[4];
            ldsm4(a, asb[st] + 2 * ((rb + 8 * (mm & 1) + rr) * 40 + 16 * kk + 8 * (mm >> 1)));
#pragma unroll
            for (int q = 0; q < 4; q++) {
                uint32_t wb[4];
                ldsm4(wb, wsb[st] + 2 * ((16 * q + 8 * (mm >> 1) + rr) * 40 + 16 * kk + 8 * (mm & 1)));
                mma_f16(s[2 * q    ], a, wb[0], wb[1]);
                mma_f16(s[2 * q + 1], a, wb[2], wb[3]);
            }
        }

        if (MODE == 0 && stage_more) sts_A0(it + 2);   // after MMAs: LDG latency hidden
    }

    // epilogue (fp32 accumulators)
    const int r0 = row0 + rb + g;
    const int r1 = r0 + 8;
    float p00 = 0, p01 = 0, p02 = 0, p10 = 0, p11 = 0, p12 = 0;
    if (MODE == 0) {
        p00 = pts[r0 * 3 + 0]; p01 = pts[r0 * 3 + 1]; p02 = pts[r0 * 3 + 2];
        p10 = pts[r1 * 3 + 0]; p11 = pts[r1 * 3 + 1]; p12 = pts[r1 * 3 + 2];
    }
#pragma unroll
    for (int nb = 0; nb < 8; nb++) {
        const int c = col0 + nb * 8 + 2 * t;
        if (MODE == 1) {
            const float b0 = bias[c], b1 = bias[c + 1];
            const int b_  = r0 >> 11;
            const int n0_ = r0 & (M_VOX - 1), n1_ = r1 & (M_VOX - 1);
            const int h = c >> 5, dh = c & 31;
            const int bh = b_ * NHEADS + h;
            if (zv == 0) {   // K: row-major fp16
                __half* dst0 = g_k16 + ((size_t)bh * M_VOX + n0_) * HD + dh;
                __half* dst1 = g_k16 + ((size_t)bh * M_VOX + n1_) * HD + dh;
                *(__half2*)dst0 = __floats2half2_rn(s[nb][0] + b0, s[nb][1] + b1);
                *(__half2*)dst1 = __floats2half2_rn(s[nb][2] + b0, s[nb][3] + b1);
            } else {         // V: transposed fp16 [bh][dh][M]
                __half* r_lo = g_v16 + ((size_t)bh * HD + dh    ) * M_VOX;
                __half* r_hi = g_v16 + ((size_t)bh * HD + dh + 1) * M_VOX;
                r_lo[n0_] = __float2half_rn(s[nb][0] + b0);
                r_hi[n0_] = __float2half_rn(s[nb][1] + b1);
                r_lo[n1_] = __float2half_rn(s[nb][2] + b0);
                r_hi[n1_] = __float2half_rn(s[nb][3] + b1);
            }
        } else {
            const float b0 = g_bfp[c], b1 = g_bfp[c + 1];
            const float w00 = g_wfp[c * 3 + 0], w01 = g_wfp[c * 3 + 1], w02 = g_wfp[c * 3 + 2];
            const float w10 = g_wfp[c * 3 + 3], w11 = g_wfp[c * 3 + 4], w12 = g_wfp[c * 3 + 5];
            float v00 = s[nb][0] + b0 + p00 * w00 + p01 * w01 + p02 * w02;
            float v01 = s[nb][1] + b1 + p00 * w10 + p01 * w11 + p02 * w12;
            float v10 = s[nb][2] + b0 + p10 * w00 + p11 * w01 + p12 * w02;
            float v11 = s[nb][3] + b1 + p10 * w10 + p11 * w11 + p12 * w12;
            *(float2*)(C + (size_t)r0 * 256 + c) = make_float2(v00, v01);
            *(float2*)(C + (size_t)r1 * 256 + c) = make_float2(v10, v11);
        }
    }
}

// ---------------------------------------------------------------------------
// Flash attention (R10, best-known): split-KV (2 splits of 16 tiles),
// 128-row Q tile, 4 warps x 32 rows, 2-stage cp.async ring, Q fused from
// points, fp16 MMA via ldmatrix, no-max base-2 softmax, l via HADD2,
// unnormalized O + l partials written per split.
// ---------------------------------------------------------------------------
__global__ void __launch_bounds__(128) attn_kernel(const float* __restrict__ pts) {
    const int h     = blockIdx.y;
    const int b     = blockIdx.z & 1;
    const int split = blockIdx.z >> 1;
    const int bh    = b * NHEADS + h;
    const int n0    = blockIdx.x * 128;
    const int tb    = split * HTILES;

    const __half* __restrict__ Kp = g_k16 + (size_t)bh * M_VOX * HD;
    const __half* __restrict__ Vp = g_v16 + (size_t)bh * HD * M_VOX;

    __shared__ __half Ks[2][64][40];
    __shared__ __half Vt[2][32][72];

    const int tid  = threadIdx.x;
    const int lane = tid & 31;
    const int warp = tid >> 5;
    const int g    = lane >> 2;
    const int t    = lane & 3;
    const int rb   = warp * 32;
    const int mm   = lane >> 3;
    const int rr   = lane & 7;

    const uint32_t ks_row = 8 * (mm >> 1) + rr;
    const uint32_t ks_col = 8 * (mm & 1);
    uint32_t ksb[2], vtb[2];
#pragma unroll
    for (int i = 0; i < 2; i++) {
        ksb[i] = (uint32_t)__cvta_generic_to_shared(&Ks[i][0][0]);
        vtb[i] = (uint32_t)__cvta_generic_to_shared(&Vt[i][0][0]);
    }

    // ---- Q fragments from points (q = pts @ Wqp^T + bqp, scale folded)
    float P[4][3];
#pragma unroll
    for (int i = 0; i < 4; i++) {
        const int n = n0 + rb + 8 * i + g;
#pragma unroll
        for (int j = 0; j < 3; j++)
            P[i][j] = pts[((size_t)b * N_PTS + n) * 3 + j];
    }
    uint32_t qa[2][2][4];
#pragma unroll
    for (int kk = 0; kk < 2; kk++) {
#pragma unroll
        for (int hw = 0; hw < 2; hw++) {
            const int c = h * HD + 16 * kk + 8 * hw + 2 * t;
            const float wa0 = g_wqp[3 * c + 0], wa1 = g_wqp[3 * c + 1], wa2 = g_wqp[3 * c + 2];
            const float wb0 = g_wqp[3 * c + 3], wb1 = g_wqp[3 * c + 4], wb2 = g_wqp[3 * c + 5];
            const float ba = g_bqp[c], bb = g_bqp[c + 1];
#pragma unroll
            for (int grp = 0; grp < 2; grp++) {
#pragma unroll
                for (int rw = 0; rw < 2; rw++) {
                    const float* p = P[2 * grp + rw];
                    float q0 = fmaf(p[0], wa0, fmaf(p[1], wa1, fmaf(p[2], wa2, ba)));
                    float q1 = fmaf(p[0], wb0, fmaf(p[1], wb1, fmaf(p[2], wb2, bb)));
                    qa[grp][kk][rw + 2 * hw] = f16pair(q0, q1);
                }
            }
        }
    }

    float o[2][4][4];
    float lsum[2][2];
#pragma unroll
    for (int grp = 0; grp < 2; grp++) {
        lsum[grp][0] = 0.0f; lsum[grp][1] = 0.0f;
#pragma unroll
        for (int nb = 0; nb < 4; nb++)
#pragma unroll
            for (int j = 0; j < 4; j++) o[grp][nb][j] = 0.0f;
    }

    auto load_tile = [&](int stg, int j0) {
#pragma unroll
        for (int i = 0; i < 2; i++) {
            const int idx = i * 128 + tid;
            const int rK = idx >> 2, cK = (idx & 3) * 8;
            cp16(&Ks[stg][rK][cK], Kp + (size_t)(j0 + rK) * HD + cK);
            const int rV = idx >> 3, cV = (idx & 7) * 8;
            cp16(&Vt[stg][rV][cV], Vp + (size_t)rV * M_VOX + j0 + cV);
        }
        CP_COMMIT();
    };

    load_tile(0, tb * 64);

    for (int it = 0; it < HTILES; it++) {
        const int st = it & 1;
        CP_WAIT(0);
        __syncthreads();
        if (it + 1 < HTILES) load_tile(st ^ 1, (tb + it + 1) * 64);

        // ---- S = Q K^T
        float s[2][8][4];
#pragma unroll
        for (int grp = 0; grp < 2; grp++)
#pragma unroll
            for (int nb = 0; nb < 8; nb++)
#pragma unroll
                for (int j = 0; j < 4; j++) s[grp][nb][j] = 0.0f;

#pragma unroll
        for (int kk = 0; kk < 2; kk++) {
#pragma unroll
            for (int q = 0; q < 4; q++) {
                uint32_t kb[4];
                const uint32_t addr = ksb[st] +
                    2 * ((16 * q + ks_row) * 40 + 16 * kk + ks_col);
                ldsm4(kb, addr);
#pragma unroll
                for (int grp = 0; grp < 2; grp++) {
                    mma_f16(s[grp][2 * q    ], qa[grp][kk], kb[0], kb[1]);
                    mma_f16(s[grp][2 * q + 1], qa[grp][kk], kb[2], kb[3]);
                }
            }
        }

        // ---- P = 2^S (fp16x2); l via HADD2; O += P V
        __half2 lt[2][2];
#pragma unroll
        for (int grp = 0; grp < 2; grp++) {
            lt[grp][0] = __floats2half2_rn(0.0f, 0.0f);
            lt[grp][1] = __floats2half2_rn(0.0f, 0.0f);
        }
#pragma unroll
        for (int jj = 0; jj < 4; jj++) {
            uint32_t pa[2][4];
#pragma unroll
            for (int grp = 0; grp < 2; grp++) {
                pa[grp][0] = ex2h2(f16pair(s[grp][2 * jj    ][0], s[grp][2 * jj    ][1]));
                pa[grp][1] = ex2h2(f16pair(s[grp][2 * jj    ][2], s[grp][2 * jj    ][3]));
                pa[grp][2] = ex2h2(f16pair(s[grp][2 * jj + 1][0], s[grp][2 * jj + 1][1]));
                pa[grp][3] = ex2h2(f16pair(s[grp][2 * jj + 1][2], s[grp][2 * jj + 1][3]));
                lt[grp][0] = __hadd2(lt[grp][0],
                    __hadd2(*(__half2*)&pa[grp][0], *(__half2*)&pa[grp][2]));
                lt[grp][1] = __hadd2(lt[grp][1],
                    __hadd2(*(__half2*)&pa[grp][1], *(__half2*)&pa[grp][3]));
            }
#pragma unroll
            for (int q = 0; q < 2; q++) {
                uint32_t vb[4];
                const uint32_t addr = vtb[st] +
                    2 * ((16 * q + ks_row) * 72 + 16 * jj + ks_col);
                ldsm4(vb, addr);
#pragma unroll
                for (int grp = 0; grp < 2; grp++) {
                    mma_f16(o[grp][2 * q    ], pa[grp], vb[0], vb[1]);
                    mma_f16(o[grp][2 * q + 1], pa[grp], vb[2], vb[3]);
                }
            }
        }
#pragma unroll
        for (int grp = 0; grp < 2; grp++) {
            lsum[grp][0] += __low2float(lt[grp][0]) + __high2float(lt[grp][0]);
            lsum[grp][1] += __low2float(lt[grp][1]) + __high2float(lt[grp][1]);
        }
    }

    // write unnormalized partials
    float* po = g_po + (size_t)split * B_SZ * N_PTS * D_MODEL;
    float* pl = g_pl + ((size_t)(split * B_SZ + b) * NHEADS + h) * N_PTS;
#pragma unroll
    for (int grp = 0; grp < 2; grp++) {
        float l0 = lsum[grp][0], l1 = lsum[grp][1];
        l0 += __shfl_xor_sync(0xffffffffu, l0, 1);
        l0 += __shfl_xor_sync(0xffffffffu, l0, 2);
        l1 += __shfl_xor_sync(0xffffffffu, l1, 1);
        l1 += __shfl_xor_sync(0xffffffffu, l1, 2);
        const int r0 = n0 + rb + 16 * grp + g;
        const int r1 = r0 + 8;
        if (t == 0) { pl[r0] = l0; pl[r1] = l1; }
#pragma unroll
        for (int nb = 0; nb < 4; nb++) {
            const int col = h * HD + nb * 8 + 2 * t;
            *(float2*)(po + (size_t)(b * N_PTS + r0) * D_MODEL + col) =
                make_float2(o[grp][nb][0], o[grp][nb][1]);
            *(float2*)(po + (size_t)(b * N_PTS + r1) * D_MODEL + col) =
                make_float2(o[grp][nb][2], o[grp][nb][3]);
        }
    }
}

// ---------------------------------------------------------------------------
// kernel_launch
// ---------------------------------------------------------------------------
extern "C" void kernel_launch(void* const* d_in, const int* in_sizes, int n_in,
                              void* d_out, int out_size) {
    const float* points = (const float*)d_in[0];
    const float* voxel  = (const float*)d_in[1];
    const float* Wp     = (const float*)d_in[2];
    const float* bp     = (const float*)d_in[3];
    const float* Wq     = (const float*)d_in[4];
    const float* bq     = (const float*)d_in[5];
    const float* Wk     = (const float*)d_in[6];
    const float* bk     = (const float*)d_in[7];
    const float* Wv     = (const float*)d_in[8];
    const float* bv     = (const float*)d_in[9];
    const float* Wf     = (const float*)d_in[10];
    const float* bf     = (const float*)d_in[11];
    float* out = (float*)d_out;

    __half *vox_ptr, *wk_ptr, *wv_ptr, *wf_ptr;
    cudaGetSymbolAddress((void**)&vox_ptr, g_vox16);
    cudaGetSymbolAddress((void**)&wk_ptr,  g_wk16);
    cudaGetSymbolAddress((void**)&wv_ptr,  g_wv16);
    cudaGetSymbolAddress((void**)&wf_ptr,  g_wf16);

    // 1. merged weight folding + fp16 conversions
    prep_cvt_kernel<<<(B_SZ * M_VOX * D_MODEL + 255) / 256, 256>>>(
        Wp, bp, Wq, bq, Wf, bf, voxel, Wk, Wv);

    // 2. k & v projections (fp16 MMA; z: 0->K row-major, 1->V transposed)
    {
        dim3 grid(D_MODEL / 64, (B_SZ * M_VOX) / 64, 2);
        gemm_f16<1><<<grid, 128>>>(vox_ptr, wk_ptr, wv_ptr, bk, bv, nullptr, nullptr);
    }
    // 3. attention (split-KV, 2-stage ring, q fused from points)
    {
        dim3 grid(N_PTS / 128, NHEADS, B_SZ * 2);
        attn_kernel<<<grid, 128>>>(points);
    }
    // 4. final: normalize(po,pl) @ Wf2^T + pts @ Wfp^T + bfp (combine fused)
    {
        dim3 grid(D_MODEL / 64, (B_SZ * N_PTS) / 64, 1);
        gemm_f16<0><<<grid, 128>>>(nullptr, wf_ptr, nullptr, nullptr, nullptr, out, points);
    }
}